// round 3
// baseline (speedup 1.0000x reference)
#include <cuda_runtime.h>
#include <cstdint>

// Volume: 256^3 voxels. Inputs (metadata order):
//   d_in[0] vessel_labels  int32   [16777216]
//   d_in[1] id_intensity   float32 [256]
//   d_in[2] id_is_dark     int32   [256]
//   d_in[3] parenchyma     float32 [16777216]
// Output (float32, 67108864): out [16.78M] then onehot [3,16.78M]
//   ch0 = background, ch1 = dark vessel, ch2 = bright vessel.

#define N_VOX (256u * 256u * 256u)
#define VEC   (N_VOX / 4u)        // 4,194,304 vec4 elements
#define TPB   256u
#define NCTA  (148u * 8u)         // one full wave at 8 CTA/SM

__global__ __launch_bounds__(TPB, 8)
void yibei_kernel(const int4* __restrict__ labels4,
                  const float4* __restrict__ par4,
                  const float* __restrict__ id_intensity,
                  const int* __restrict__ id_is_dark,
                  float* __restrict__ out)
{
    // Fused LUT in shared: .x = intensity bits (id 0 forced to 1.0f), .y = dark flag
    __shared__ uint2 s_lut[256];
    {
        int t = threadIdx.x;   // blockDim.x == 256
        float inten = (t == 0) ? 1.0f : __ldg(&id_intensity[t]);
        s_lut[t] = make_uint2(__float_as_uint(inten), (unsigned)__ldg(&id_is_dark[t]));
    }
    __syncthreads();

    const unsigned stride = NCTA * TPB;                    // 303,104 vec4 / iter
    unsigned i = blockIdx.x * TPB + threadIdx.x;
    float4* o4 = (float4*)out;

    if (i >= VEC) return;

    // Software pipeline: loads for the NEXT tile are issued before stores of
    // the CURRENT tile, keeping reads continuously in flight against writes.
    int4   lab = __ldcs(&labels4[i]);
    float4 p   = __ldcs(&par4[i]);

    while (true) {
        unsigned inext = i + stride;
        int4   lab_n;
        float4 p_n;
        bool have_next = (inext < VEC);
        if (have_next) {
            lab_n = __ldcs(&labels4[inext]);
            p_n   = __ldcs(&par4[inext]);
        }

        float4 o, c0, c1, c2;
        #pragma unroll
        for (int k = 0; k < 4; ++k) {
            int   l  = (&lab.x)[k];
            float pv = (&p.x)[k];
            uint2 e  = s_lut[l];
            bool  m  = (l != 0);
            bool  d  = m & (e.y == 1u);
            (&o.x)[k]  = pv * __uint_as_float(e.x);   // lut[0] == 1.0 -> branch-free
            (&c0.x)[k] = m ? 0.0f : 1.0f;
            (&c1.x)[k] = d ? 1.0f : 0.0f;
            (&c2.x)[k] = (m & !d) ? 1.0f : 0.0f;
        }

        __stcs(&o4[i],            o);
        __stcs(&o4[VEC + i],      c0);
        __stcs(&o4[2u * VEC + i], c1);
        __stcs(&o4[3u * VEC + i], c2);

        if (!have_next) break;
        i   = inext;
        lab = lab_n;
        p   = p_n;
    }
}

extern "C" void kernel_launch(void* const* d_in, const int* in_sizes, int n_in,
                              void* d_out, int out_size)
{
    const int4*   labels4 = (const int4*)d_in[0];
    const float*  id_int  = (const float*)d_in[1];
    const int*    id_dark = (const int*)d_in[2];
    const float4* par4    = (const float4*)d_in[3];
    float*        out     = (float*)d_out;

    yibei_kernel<<<NCTA, TPB>>>(labels4, par4, id_int, id_dark, out);
}

// round 4
// speedup vs baseline: 1.1244x; 1.1244x over previous
#include <cuda_runtime.h>
#include <cstdint>

// Volume: 256^3 voxels. Inputs (metadata order):
//   d_in[0] vessel_labels  int32   [16777216]
//   d_in[1] id_intensity   float32 [256]
//   d_in[2] id_is_dark     int32   [256]
//   d_in[3] parenchyma     float32 [16777216]
// Output (float32, 67108864): out [16.78M] then onehot [3,16.78M]
//   ch0 = background, ch1 = dark vessel, ch2 = bright vessel.

#define N_VOX (256u * 256u * 256u)
#define VEC8  (N_VOX / 8u)        // 2,097,152 vec8 tiles
#define TPB   256u
#define BLOCKS (VEC8 / TPB)       // 8192

// 256-bit global load/store (sm_100+: LDG.E.256 / STG.E.256), streaming (.cs).
__device__ __forceinline__ void ldg256_cs(const void* p, uint4& a, uint4& b) {
    asm volatile("ld.global.cs.v8.b32 {%0,%1,%2,%3,%4,%5,%6,%7}, [%8];"
                 : "=r"(a.x), "=r"(a.y), "=r"(a.z), "=r"(a.w),
                   "=r"(b.x), "=r"(b.y), "=r"(b.z), "=r"(b.w)
                 : "l"(p));
}
__device__ __forceinline__ void stg256_cs(void* p, const uint4& a, const uint4& b) {
    asm volatile("st.global.cs.v8.b32 [%0], {%1,%2,%3,%4,%5,%6,%7,%8};"
                 :: "l"(p),
                    "r"(a.x), "r"(a.y), "r"(a.z), "r"(a.w),
                    "r"(b.x), "r"(b.y), "r"(b.z), "r"(b.w)
                 : "memory");
}

__global__ __launch_bounds__(TPB, 8)
void yibei_kernel(const int* __restrict__ labels,
                  const float* __restrict__ par,
                  const float* __restrict__ id_intensity,
                  const int* __restrict__ id_is_dark,
                  float* __restrict__ out)
{
    // Fused LUT in shared: .x = intensity bits (id 0 forced to 1.0f), .y = dark flag
    __shared__ uint2 s_lut[256];
    {
        int t = threadIdx.x;   // blockDim.x == 256
        float inten = (t == 0) ? 1.0f : __ldg(&id_intensity[t]);
        s_lut[t] = make_uint2(__float_as_uint(inten), (unsigned)__ldg(&id_is_dark[t]));
    }
    __syncthreads();

    unsigned i = blockIdx.x * TPB + threadIdx.x;   // vec8 tile index
    size_t e = (size_t)i * 8u;                     // element offset

    // 32B-per-lane streaming loads: one LDG.256 per input stream.
    uint4 labA, labB, pA, pB;
    ldg256_cs(labels + e, labA, labB);
    ldg256_cs(par + e,    pA,  pB);

    uint4 oA, oB, c0A, c0B, c1A, c1B, c2A, c2B;

    #pragma unroll
    for (int k = 0; k < 8; ++k) {
        int   l  = (int)((k < 4) ? (&labA.x)[k] : (&labB.x)[k - 4]);
        float pv = __uint_as_float((k < 4) ? (&pA.x)[k] : (&pB.x)[k - 4]);
        uint2 ent = s_lut[l];
        bool  m  = (l != 0);
        bool  d  = m & (ent.y == 1u);
        unsigned ov  = __float_as_uint(pv * __uint_as_float(ent.x)); // lut[0]==1.0
        unsigned b0  = __float_as_uint(m ? 0.0f : 1.0f);
        unsigned b1  = __float_as_uint(d ? 1.0f : 0.0f);
        unsigned b2  = __float_as_uint((m & !d) ? 1.0f : 0.0f);
        if (k < 4) {
            (&oA.x)[k]  = ov;  (&c0A.x)[k] = b0;
            (&c1A.x)[k] = b1;  (&c2A.x)[k] = b2;
        } else {
            (&oB.x)[k-4]  = ov;  (&c0B.x)[k-4] = b0;
            (&c1B.x)[k-4] = b1;  (&c2B.x)[k-4] = b2;
        }
    }

    stg256_cs(out + e,                      oA,  oB);
    stg256_cs(out + (size_t)N_VOX + e,      c0A, c0B);
    stg256_cs(out + 2u * (size_t)N_VOX + e, c1A, c1B);
    stg256_cs(out + 3u * (size_t)N_VOX + e, c2A, c2B);
}

extern "C" void kernel_launch(void* const* d_in, const int* in_sizes, int n_in,
                              void* d_out, int out_size)
{
    const int*   labels = (const int*)d_in[0];
    const float* id_int = (const float*)d_in[1];
    const int*   id_dark= (const int*)d_in[2];
    const float* par    = (const float*)d_in[3];
    float*       out    = (float*)d_out;

    yibei_kernel<<<BLOCKS, TPB>>>(labels, par, id_int, id_dark, out);
}

// round 5
// speedup vs baseline: 1.1485x; 1.0214x over previous
#include <cuda_runtime.h>
#include <cstdint>

// Volume: 256^3 voxels. Inputs (metadata order):
//   d_in[0] vessel_labels  int32   [16777216]
//   d_in[1] id_intensity   float32 [256]
//   d_in[2] id_is_dark     int32   [256]
//   d_in[3] parenchyma     float32 [16777216]
// Output (float32, 67108864): out [16.78M] then onehot [3,16.78M]
//   ch0 = background, ch1 = dark vessel, ch2 = bright vessel.

#define N_VOX (256u * 256u * 256u)
#define VEC   (N_VOX / 4u)        // 4,194,304 vec4 elements
#define TPB   256u
#define ITEMS 2u                  // vec4 tiles per thread
#define BLOCKS (VEC / (TPB * ITEMS))   // 8192

__global__ __launch_bounds__(TPB, 8)
void yibei_kernel(const int4* __restrict__ labels4,
                  const float4* __restrict__ par4,
                  const float* __restrict__ id_intensity,
                  const int* __restrict__ id_is_dark,
                  float* __restrict__ out)
{
    // Fused LUT in shared: .x = intensity bits (id 0 forced to 1.0f), .y = dark flag
    __shared__ uint2 s_lut[256];
    {
        int t = threadIdx.x;   // blockDim.x == 256
        float inten = (t == 0) ? 1.0f : __ldg(&id_intensity[t]);
        s_lut[t] = make_uint2(__float_as_uint(inten), (unsigned)__ldg(&id_is_dark[t]));
    }
    __syncthreads();

    // Two contiguous-per-warp tiles, TPB apart: all accesses 128B-coalesced,
    // and per-stream store pairs form 1KB-contiguous warp bursts.
    unsigned base = blockIdx.x * (TPB * ITEMS) + threadIdx.x;
    unsigned i0 = base;
    unsigned i1 = base + TPB;

    // Front-batch all global loads (MLP = 4).
    int4   lab0 = __ldcs(&labels4[i0]);
    int4   lab1 = __ldcs(&labels4[i1]);
    float4 p0   = __ldcs(&par4[i0]);
    float4 p1   = __ldcs(&par4[i1]);

    // Per-lane classification, kept in small arrays (registers after unroll).
    float s0[4], s1[4];
    bool  m0[4], m1[4], d0[4], d1[4];
    #pragma unroll
    for (int k = 0; k < 4; ++k) {
        int l0 = (&lab0.x)[k];
        int l1 = (&lab1.x)[k];
        uint2 e0 = s_lut[l0];
        uint2 e1 = s_lut[l1];
        s0[k] = __uint_as_float(e0.x);   // lut[0] == 1.0 -> branch-free scale
        s1[k] = __uint_as_float(e1.x);
        m0[k] = (l0 != 0);               m1[k] = (l1 != 0);
        d0[k] = m0[k] & (e0.y == 1u);    d1[k] = m1[k] & (e1.y == 1u);
    }

    float4* o4 = (float4*)out;
    float4 a, b;

    // Stream 0: scaled parenchyma (grouped: both tiles back-to-back)
    #pragma unroll
    for (int k = 0; k < 4; ++k) { (&a.x)[k] = (&p0.x)[k] * s0[k];
                                  (&b.x)[k] = (&p1.x)[k] * s1[k]; }
    __stcs(&o4[i0], a);
    __stcs(&o4[i1], b);

    // Stream 1: background channel
    #pragma unroll
    for (int k = 0; k < 4; ++k) { (&a.x)[k] = m0[k] ? 0.0f : 1.0f;
                                  (&b.x)[k] = m1[k] ? 0.0f : 1.0f; }
    __stcs(&o4[VEC + i0], a);
    __stcs(&o4[VEC + i1], b);

    // Stream 2: dark-vessel channel
    #pragma unroll
    for (int k = 0; k < 4; ++k) { (&a.x)[k] = d0[k] ? 1.0f : 0.0f;
                                  (&b.x)[k] = d1[k] ? 1.0f : 0.0f; }
    __stcs(&o4[2u * VEC + i0], a);
    __stcs(&o4[2u * VEC + i1], b);

    // Stream 3: bright-vessel channel
    #pragma unroll
    for (int k = 0; k < 4; ++k) { (&a.x)[k] = (m0[k] & !d0[k]) ? 1.0f : 0.0f;
                                  (&b.x)[k] = (m1[k] & !d1[k]) ? 1.0f : 0.0f; }
    __stcs(&o4[3u * VEC + i0], a);
    __stcs(&o4[3u * VEC + i1], b);
}

extern "C" void kernel_launch(void* const* d_in, const int* in_sizes, int n_in,
                              void* d_out, int out_size)
{
    const int4*   labels4 = (const int4*)d_in[0];
    const float*  id_int  = (const float*)d_in[1];
    const int*    id_dark = (const int*)d_in[2];
    const float4* par4    = (const float4*)d_in[3];
    float*        out     = (float*)d_out;

    yibei_kernel<<<BLOCKS, TPB>>>(labels4, par4, id_int, id_dark, out);
}

// round 6
// speedup vs baseline: 1.1525x; 1.0035x over previous
#include <cuda_runtime.h>
#include <cstdint>

// Volume: 256^3 voxels. Inputs (metadata order):
//   d_in[0] vessel_labels  int32   [16777216]
//   d_in[1] id_intensity   float32 [256]
//   d_in[2] id_is_dark     int32   [256]
//   d_in[3] parenchyma     float32 [16777216]
// Output (float32, 67108864): out [16.78M] then onehot [3,16.78M]
//   ch0 = background, ch1 = dark vessel, ch2 = bright vessel.

#define N_VOX (256u * 256u * 256u)
#define VEC   (N_VOX / 4u)             // 4,194,304 vec4 elements
#define TPB   128u
#define ITEMS 4u                       // vec4 tiles per thread
#define BLOCKS (VEC / (TPB * ITEMS))   // 8192

__global__ __launch_bounds__(TPB, 8)
void yibei_kernel(const int4* __restrict__ labels4,
                  const float4* __restrict__ par4,
                  const float* __restrict__ id_intensity,
                  const int* __restrict__ id_is_dark,
                  float* __restrict__ out)
{
    // Fused LUT in shared: .x = intensity bits (id 0 forced to 1.0f), .y = dark flag
    __shared__ uint2 s_lut[256];
    {
        int t = threadIdx.x;           // TPB == 128: two entries per thread
        #pragma unroll
        for (int j = 0; j < 2; ++j) {
            int id = t + j * 128;
            float inten = (id == 0) ? 1.0f : __ldg(&id_intensity[id]);
            s_lut[id] = make_uint2(__float_as_uint(inten), (unsigned)__ldg(&id_is_dark[id]));
        }
    }
    __syncthreads();

    // Four contiguous-per-warp tiles, TPB apart: all accesses 128B-coalesced;
    // per-stream grouped stores form 2KB-contiguous warp bursts.
    unsigned base = blockIdx.x * (TPB * ITEMS) + threadIdx.x;
    unsigned idx[ITEMS];
    #pragma unroll
    for (int t = 0; t < (int)ITEMS; ++t) idx[t] = base + t * TPB;

    // Front-batch all global loads (MLP = 8).
    int4   lab[ITEMS];
    float4 p[ITEMS];
    #pragma unroll
    for (int t = 0; t < (int)ITEMS; ++t) lab[t] = __ldcs(&labels4[idx[t]]);
    #pragma unroll
    for (int t = 0; t < (int)ITEMS; ++t) p[t]   = __ldcs(&par4[idx[t]]);

    // Per-lane classification (registers after unroll).
    float s[ITEMS][4];
    bool  m[ITEMS][4], d[ITEMS][4];
    #pragma unroll
    for (int t = 0; t < (int)ITEMS; ++t) {
        #pragma unroll
        for (int k = 0; k < 4; ++k) {
            int l = (&lab[t].x)[k];
            uint2 e = s_lut[l];
            s[t][k] = __uint_as_float(e.x);      // lut[0] == 1.0 -> branch-free
            m[t][k] = (l != 0);
            d[t][k] = m[t][k] & (e.y == 1u);
        }
    }

    float4* o4 = (float4*)out;
    float4 v;

    // Stream 0: scaled parenchyma (all 4 tiles back-to-back)
    #pragma unroll
    for (int t = 0; t < (int)ITEMS; ++t) {
        #pragma unroll
        for (int k = 0; k < 4; ++k) (&v.x)[k] = (&p[t].x)[k] * s[t][k];
        __stcs(&o4[idx[t]], v);
    }
    // Stream 1: background channel
    #pragma unroll
    for (int t = 0; t < (int)ITEMS; ++t) {
        #pragma unroll
        for (int k = 0; k < 4; ++k) (&v.x)[k] = m[t][k] ? 0.0f : 1.0f;
        __stcs(&o4[VEC + idx[t]], v);
    }
    // Stream 2: dark-vessel channel
    #pragma unroll
    for (int t = 0; t < (int)ITEMS; ++t) {
        #pragma unroll
        for (int k = 0; k < 4; ++k) (&v.x)[k] = d[t][k] ? 1.0f : 0.0f;
        __stcs(&o4[2u * VEC + idx[t]], v);
    }
    // Stream 3: bright-vessel channel
    #pragma unroll
    for (int t = 0; t < (int)ITEMS; ++t) {
        #pragma unroll
        for (int k = 0; k < 4; ++k) (&v.x)[k] = (m[t][k] & !d[t][k]) ? 1.0f : 0.0f;
        __stcs(&o4[3u * VEC + idx[t]], v);
    }
}

extern "C" void kernel_launch(void* const* d_in, const int* in_sizes, int n_in,
                              void* d_out, int out_size)
{
    const int4*   labels4 = (const int4*)d_in[0];
    const float*  id_int  = (const float*)d_in[1];
    const int*    id_dark = (const int*)d_in[2];
    const float4* par4    = (const float4*)d_in[3];
    float*        out     = (float*)d_out;

    yibei_kernel<<<BLOCKS, TPB>>>(labels4, par4, id_int, id_dark, out);
}

// round 7
// speedup vs baseline: 1.1537x; 1.0010x over previous
#include <cuda_runtime.h>
#include <cstdint>

// Volume: 256^3 voxels. Inputs (metadata order):
//   d_in[0] vessel_labels  int32   [16777216]
//   d_in[1] id_intensity   float32 [256]
//   d_in[2] id_is_dark     int32   [256]
//   d_in[3] parenchyma     float32 [16777216]
// Output (float32, 67108864): out [16.78M] then onehot [3,16.78M]
//   ch0 = background, ch1 = dark vessel, ch2 = bright vessel.

#define N_VOX (256u * 256u * 256u)
#define VEC   (N_VOX / 4u)             // 4,194,304 vec4 elements
#define TPB   512u
#define ITEMS 2u                       // vec4 tiles per thread
#define BLOCKS (VEC / (TPB * ITEMS))   // 4096

__global__ __launch_bounds__(TPB, 4)
void yibei_kernel(const int4* __restrict__ labels4,
                  const float4* __restrict__ par4,
                  const float* __restrict__ id_intensity,
                  const int* __restrict__ id_is_dark,
                  float* __restrict__ out)
{
    // Fused LUT in shared: .x = intensity bits (id 0 forced to 1.0f), .y = dark flag
    __shared__ uint2 s_lut[256];
    if (threadIdx.x < 256u) {
        int t = threadIdx.x;
        float inten = (t == 0) ? 1.0f : __ldg(&id_intensity[t]);
        s_lut[t] = make_uint2(__float_as_uint(inten), (unsigned)__ldg(&id_is_dark[t]));
    }
    __syncthreads();

    // Two contiguous-per-warp tiles, TPB apart: all accesses 128B-coalesced,
    // and per-stream store pairs form 1KB-contiguous warp bursts.
    unsigned base = blockIdx.x * (TPB * ITEMS) + threadIdx.x;
    unsigned i0 = base;
    unsigned i1 = base + TPB;

    // Front-batch all global loads (MLP = 4).
    int4   lab0 = __ldcs(&labels4[i0]);
    int4   lab1 = __ldcs(&labels4[i1]);
    float4 p0   = __ldcs(&par4[i0]);
    float4 p1   = __ldcs(&par4[i1]);

    // Per-lane classification, kept in registers after unroll.
    float s0[4], s1[4];
    bool  m0[4], m1[4], d0[4], d1[4];
    #pragma unroll
    for (int k = 0; k < 4; ++k) {
        int l0 = (&lab0.x)[k];
        int l1 = (&lab1.x)[k];
        uint2 e0 = s_lut[l0];
        uint2 e1 = s_lut[l1];
        s0[k] = __uint_as_float(e0.x);   // lut[0] == 1.0 -> branch-free scale
        s1[k] = __uint_as_float(e1.x);
        m0[k] = (l0 != 0);               m1[k] = (l1 != 0);
        d0[k] = m0[k] & (e0.y == 1u);    d1[k] = m1[k] & (e1.y == 1u);
    }

    float4* o4 = (float4*)out;
    float4 a, b;

    // Stream 0: scaled parenchyma (grouped: both tiles back-to-back)
    #pragma unroll
    for (int k = 0; k < 4; ++k) { (&a.x)[k] = (&p0.x)[k] * s0[k];
                                  (&b.x)[k] = (&p1.x)[k] * s1[k]; }
    __stcs(&o4[i0], a);
    __stcs(&o4[i1], b);

    // Stream 1: background channel
    #pragma unroll
    for (int k = 0; k < 4; ++k) { (&a.x)[k] = m0[k] ? 0.0f : 1.0f;
                                  (&b.x)[k] = m1[k] ? 0.0f : 1.0f; }
    __stcs(&o4[VEC + i0], a);
    __stcs(&o4[VEC + i1], b);

    // Stream 2: dark-vessel channel
    #pragma unroll
    for (int k = 0; k < 4; ++k) { (&a.x)[k] = d0[k] ? 1.0f : 0.0f;
                                  (&b.x)[k] = d1[k] ? 1.0f : 0.0f; }
    __stcs(&o4[2u * VEC + i0], a);
    __stcs(&o4[2u * VEC + i1], b);

    // Stream 3: bright-vessel channel
    #pragma unroll
    for (int k = 0; k < 4; ++k) { (&a.x)[k] = (m0[k] & !d0[k]) ? 1.0f : 0.0f;
                                  (&b.x)[k] = (m1[k] & !d1[k]) ? 1.0f : 0.0f; }
    __stcs(&o4[3u * VEC + i0], a);
    __stcs(&o4[3u * VEC + i1], b);
}

extern "C" void kernel_launch(void* const* d_in, const int* in_sizes, int n_in,
                              void* d_out, int out_size)
{
    const int4*   labels4 = (const int4*)d_in[0];
    const float*  id_int  = (const float*)d_in[1];
    const int*    id_dark = (const int*)d_in[2];
    const float4* par4    = (const float4*)d_in[3];
    float*        out     = (float*)d_out;

    yibei_kernel<<<BLOCKS, TPB>>>(labels4, par4, id_int, id_dark, out);
}